// round 13
// baseline (speedup 1.0000x reference)
#include <cuda_runtime.h>
#include <cuda_fp16.h>
#include <cstdint>

#define BATCH 256
#define ISZ   512
#define STEPS 256
#define HID   512
#define GH    1536
#define MROWS (STEPS * BATCH)     // 65536

// ---------------- scratch ----------------
__device__ __half g_x16[(size_t)MROWS * ISZ];
__device__ __half g_w16[(size_t)GH * ISZ];
__device__ __half g_gih[(size_t)MROWS * GH];     // gi in fp16 (no bias)
__device__ __half g_h16[2][BATCH * HID];
__device__ unsigned g_bg_cnt[8];                 // zeroed each replay by k_w_convert

// ---------------- helpers ----------------
__device__ __forceinline__ uint32_t smem_to_u32(const void* p) {
    uint32_t a;
    asm("{ .reg .u64 t; cvta.to.shared.u64 t, %1; cvt.u32.u64 %0, t; }" : "=r"(a) : "l"(p));
    return a;
}
__device__ __forceinline__ void cp16(uint32_t dst, const void* src) {
    asm volatile("cp.async.cg.shared.global [%0], [%1], 16;" :: "r"(dst), "l"(src));
}
#define CP_COMMIT() asm volatile("cp.async.commit_group;" ::: "memory")
#define CP_WAIT(n)  asm volatile("cp.async.wait_group %0;" :: "n"(n) : "memory")

__device__ __forceinline__ void ldsm_x4(uint32_t addr, uint32_t r[4]) {
    asm volatile("ldmatrix.sync.aligned.m8n8.x4.shared.b16 {%0,%1,%2,%3}, [%4];"
                 : "=r"(r[0]), "=r"(r[1]), "=r"(r[2]), "=r"(r[3]) : "r"(addr));
}
__device__ __forceinline__ void ldsm_x2(uint32_t addr, uint32_t r[2]) {
    asm volatile("ldmatrix.sync.aligned.m8n8.x2.shared.b16 {%0,%1}, [%2];"
                 : "=r"(r[0]), "=r"(r[1]) : "r"(addr));
}
__device__ __forceinline__ void mma_f16(float d[4], const uint32_t a[4], const uint32_t b[2]) {
    asm volatile("mma.sync.aligned.m16n8k16.row.col.f32.f16.f16.f32 "
                 "{%0,%1,%2,%3}, {%4,%5,%6,%7}, {%8,%9}, {%0,%1,%2,%3};"
                 : "+f"(d[0]), "+f"(d[1]), "+f"(d[2]), "+f"(d[3])
                 : "r"(a[0]), "r"(a[1]), "r"(a[2]), "r"(a[3]), "r"(b[0]), "r"(b[1]));
}
__device__ __forceinline__ float fast_sigmoid(float v) {
    return __fdividef(1.f, 1.f + __expf(-v));
}
__device__ __forceinline__ float fast_tanh(float v) {
    float e = __expf(-2.f * v);
    return __fdividef(1.f - e, 1.f + e);
}

// ---------------- Wih -> fp16 + barrier counter reset ----------------
__global__ void k_w_convert(const float* __restrict__ wih) {
    if (blockIdx.x == 0 && threadIdx.x < 8)
        g_bg_cnt[threadIdx.x] = 0;                 // stream-ordered before recurrence
    size_t i = (size_t)blockIdx.x * 1024 + threadIdx.x * 4;
    #pragma unroll
    for (int j = 0; j < 4; ++j)
        g_w16[i + j] = __float2half_rn(wih[i + j]);
}

// ---------------- x [B][I][S] -> g_x16 [(s*B+b)][i] fp16 ----------------
__global__ void k_x_transpose(const float* __restrict__ x) {
    __shared__ float tile[32][33];
    int s0 = blockIdx.x * 32;
    int i0 = blockIdx.y * 32;
    int b  = blockIdx.z;
    int tx = threadIdx.x, ty = threadIdx.y;
    #pragma unroll
    for (int j = 0; j < 4; ++j)
        tile[ty + 8 * j][tx] = x[((size_t)b * ISZ + i0 + ty + 8 * j) * STEPS + s0 + tx];
    __syncthreads();
    #pragma unroll
    for (int j = 0; j < 4; ++j) {
        int s = s0 + ty + 8 * j;
        float v = tile[tx][ty + 8 * j];
        g_x16[((size_t)s * BATCH + b) * ISZ + i0 + tx] = __float2half_rn(v);
    }
}

// ---------------- HMMA GEMM: gi = x(fp16) @ Wih(fp16)^T  (fp16 out, no bias) -------
#define SA 72
#define ATILE_B (128 * SA * 2)
#define GEMM_SMEM (2 * 2 * ATILE_B)

__device__ __forceinline__ void gi_issue_load(uint32_t sb, int tid, int m0, int n0,
                                              int chunk, int buf) {
    const int k0 = chunk * 64;
    const __half* srcs[2] = {g_x16, g_w16};
    const int rowbase[2] = {m0, n0};
    #pragma unroll
    for (int t = 0; t < 2; ++t) {
        const __half* src = srcs[t];
        uint32_t dst0 = sb + buf * 2 * ATILE_B + t * ATILE_B;
        #pragma unroll
        for (int i = 0; i < 4; ++i) {
            int lin = tid + 256 * i;
            int row = lin >> 3;
            int cq  = lin & 7;
            cp16(dst0 + row * (SA * 2) + cq * 16,
                 src + (size_t)(rowbase[t] + row) * ISZ + k0 + cq * 8);
        }
    }
}

__global__ void __launch_bounds__(256) k_gemm_gi() {
    extern __shared__ char smem[];
    uint32_t sb = smem_to_u32(smem);
    const int tid = threadIdx.x;
    const int lane = tid & 31;
    const int wid = tid >> 5;
    const int wm = wid & 3;
    const int wn = wid >> 2;
    const int m0 = blockIdx.y * 128;
    const int n0 = blockIdx.x * 128;

    const int t4 = lane >> 3;
    const int arow = (t4 & 1) * 8 + (lane & 7);
    const int acol = (t4 >> 1) * 8;
    const int brow = (t4 >> 1) * 8 + (lane & 7);
    const int bcol = (t4 & 1) * 8;

    float acc[2][8][4];
    #pragma unroll
    for (int i = 0; i < 2; ++i)
        #pragma unroll
        for (int j = 0; j < 8; ++j)
            #pragma unroll
            for (int v = 0; v < 4; ++v) acc[i][j][v] = 0.f;

    gi_issue_load(sb, tid, m0, n0, 0, 0);
    CP_COMMIT();

    for (int c = 0; c < 8; ++c) {
        if (c < 7) {
            gi_issue_load(sb, tid, m0, n0, c + 1, (c + 1) & 1);
            CP_COMMIT();
            CP_WAIT(1);
        } else {
            CP_WAIT(0);
        }
        __syncthreads();
        const int buf = c & 1;
        const uint32_t bufb = sb + buf * 2 * ATILE_B;

        #pragma unroll
        for (int kk = 0; kk < 64; kk += 16) {
            uint32_t Ax[2][4], Bx[8][2];
            #pragma unroll
            for (int mt = 0; mt < 2; ++mt) {
                uint32_t r = (wm * 32 + mt * 16 + arow) * (SA * 2) + (kk + acol) * 2;
                ldsm_x4(bufb + 0 * ATILE_B + r, Ax[mt]);
            }
            #pragma unroll
            for (int pt = 0; pt < 4; ++pt) {
                uint32_t r = (wn * 64 + pt * 16 + brow) * (SA * 2) + (kk + bcol) * 2;
                uint32_t q[4];
                ldsm_x4(bufb + 1 * ATILE_B + r, q);
                Bx[2 * pt][0] = q[0]; Bx[2 * pt][1] = q[1];
                Bx[2 * pt + 1][0] = q[2]; Bx[2 * pt + 1][1] = q[3];
            }
            #pragma unroll
            for (int mt = 0; mt < 2; ++mt)
                #pragma unroll
                for (int nt = 0; nt < 8; ++nt)
                    mma_f16(acc[mt][nt], Ax[mt], Bx[nt]);
        }
        __syncthreads();
    }

    #pragma unroll
    for (int nt = 0; nt < 8; ++nt) {
        int n_base = n0 + wn * 64 + nt * 8 + (lane & 3) * 2;
        #pragma unroll
        for (int mt = 0; mt < 2; ++mt) {
            int m_base = m0 + wm * 32 + mt * 16 + (lane >> 2);
            __half2 v0 = __floats2half2_rn(acc[mt][nt][0], acc[mt][nt][1]);
            __half2 v1 = __floats2half2_rn(acc[mt][nt][2], acc[mt][nt][3]);
            *(__half2*)(g_gih + (size_t)m_base * GH + n_base) = v0;
            *(__half2*)(g_gih + (size_t)(m_base + 8) * GH + n_base) = v1;
        }
    }
}

// ---------------- persistent GRU recurrence v11: 2 CTAs/SM latency hiding ----------
// 256 CTAs (128 thr) = 8 batch-groups (32 rows) x 32 col-groups (16 cols, 48 N-rows).
// Co-resident CTAs are (almost always) different bg chains -> stalls of one chain
// hide under the other's MMAs. Barrier: per-bg monotonic REDG counter, 32 arrivals.
__device__ __forceinline__ void cntbar(int bg, unsigned target) {
    __syncthreads();
    if (threadIdx.x == 0) {
        asm volatile("red.release.gpu.global.add.u32 [%0], %1;"
                     :: "l"(&g_bg_cnt[bg]), "r"(1u) : "memory");
        unsigned v;
        do {
            asm volatile("ld.global.acquire.gpu.u32 %0, [%1];"
                         : "=r"(v) : "l"(&g_bg_cnt[bg]) : "memory");
        } while (v < target);
    }
    __syncthreads();
}

#define A_OFF 0
#define B_OFF 32768                      // A: 32 rows x 1024 B
#define BSTR 520
#define GH_OFF (B_OFF + 48 * BSTR * 2)   // 82688
#define GH_STR 50
#define REC2_SMEM (GH_OFF + 32 * GH_STR * 4)   // 89088 -> 2 CTAs/SM

__device__ __forceinline__ uint32_t a_off(int row, int kb) {
    uint32_t u = ((uint32_t)kb >> 3) ^ (row & 7);
    return (uint32_t)row * 1024 + u * 16;
}

__global__ void __launch_bounds__(128, 2) k_gru_recur(
    const float* __restrict__ whh, const float* __restrict__ bih,
    const float* __restrict__ bhh, float* __restrict__ out)
{
    extern __shared__ char smem[];
    uint32_t sb = smem_to_u32(smem);
    float* gh = (float*)(smem + GH_OFF);

    const int cta = blockIdx.x;
    const int cg  = cta & 31;
    const int bg0 = cta >> 5;        // 0..7
    const int tid = threadIdx.x;
    const int lane = tid & 31;
    const int wid = tid >> 5;        // 0..3
    const int wm = wid & 1;          // 2 m-splits of 16
    const int wn = wid >> 1;         // 2 n-splits of 24

    const int t4 = lane >> 3;
    const int arow = (t4 & 1) * 8 + (lane & 7);
    const int acol = (t4 >> 1) * 8;
    const int brow = (t4 >> 1) * 8 + (lane & 7);
    const int bcol = (t4 & 1) * 8;
    const int brow2 = lane & 7;
    const int bcol2 = ((lane >> 3) & 1) * 8;

    // resident Whh slice -> fp16: B row r = g*16+c (gate-major, as proven)
    for (int idx = tid; idx < 48 * 128; idx += 128) {
        int r = idx >> 7;
        int kq = idx & 127;
        int g = r >> 4, c = r & 15;
        float4 v = *(const float4*)(whh + (size_t)(g * HID + cg * 16 + c) * HID + kq * 4);
        __half h4[4];
        h4[0] = __float2half_rn(v.x);
        h4[1] = __float2half_rn(v.y);
        h4[2] = __float2half_rn(v.z);
        h4[3] = __float2half_rn(v.w);
        *(uint2*)(smem + B_OFF + r * (BSTR * 2) + kq * 8) = *(uint2*)h4;
    }

    const int gb = tid >> 2;         // local batch row 0..31
    const int cq = tid & 3;
    const int c0 = cq * 4;
    const int gcol0 = cg * 16 + c0;
    // folded gate biases: r,z fold bih+bhh; n keeps separate (r multiplies bhh_n)
    float brt[4], bzt[4], bni[4], bnh[4];
    #pragma unroll
    for (int i = 0; i < 4; ++i) {
        brt[i] = bih[gcol0 + i] + bhh[gcol0 + i];
        bzt[i] = bih[HID + gcol0 + i] + bhh[HID + gcol0 + i];
        bni[i] = bih[2 * HID + gcol0 + i];
        bnh[i] = bhh[2 * HID + gcol0 + i];
    }

    {   // zero h fp16 buffer 0: 256 CTAs x 128 thr x 8B = 256KB (exact)
        uint2 z = make_uint2(0, 0);
        *(uint2*)((char*)g_h16[0] + ((size_t)cta * 128 + tid) * 8) = z;
    }
    float h_old[4] = {0.f, 0.f, 0.f, 0.f};

    cntbar(bg0, 32u);           // startup barrier (counter pre-zeroed this replay)

    const uint32_t bof = sb + B_OFF;
    const int nb = wn * 24;
    const int bglob = bg0 * 32 + gb;

    for (int s = 0; s < STEPS; ++s) {
        const int cur = s & 1, nxt = cur ^ 1;
        const __half* hsrc = g_h16[cur];

        // issue all 4 A chunks (32 rows x 128 k each = 512 cp16, 4/thread)
        #pragma unroll
        for (int pre = 0; pre < 4; ++pre) {
            #pragma unroll
            for (int i = 0; i < 4; ++i) {
                int lin = tid + 128 * i;            // 0..511
                int row = lin >> 4;                 // 0..31
                int kb = pre * 128 + (lin & 15) * 8;
                cp16(sb + A_OFF + a_off(row, kb),
                     hsrc + (size_t)(bg0 * 32 + row) * HID + kb);
            }
            CP_COMMIT();
        }

        // gi prefetch (fp16, 4 cols per gate)
        const __half* gip = g_gih + ((size_t)s * BATCH + bglob) * GH;
        uint2 gru = __ldcg((const uint2*)(gip + gcol0));
        uint2 gzu = __ldcg((const uint2*)(gip + HID + gcol0));
        uint2 gnu = __ldcg((const uint2*)(gip + 2 * HID + gcol0));

        float acc[3][4];
        #pragma unroll
        for (int j = 0; j < 3; ++j)
            #pragma unroll
            for (int v = 0; v < 4; ++v) acc[j][v] = 0.f;

        #pragma unroll
        for (int kc = 0; kc < 4; ++kc) {
            if (kc == 0)      CP_WAIT(3);
            else if (kc == 1) CP_WAIT(2);
            else if (kc == 2) CP_WAIT(1);
            else              CP_WAIT(0);
            __syncthreads();

            #pragma unroll
            for (int t = 0; t < 8; ++t) {
                const int kk = kc * 128 + t * 16;
                uint32_t Ax[4], Bx[3][2];
                {
                    int rr = wm * 16 + arow;
                    ldsm_x4(sb + A_OFF + a_off(rr, kk + acol), Ax);
                }
                {
                    uint32_t q[4];
                    uint32_t r16 = (nb + brow) * (BSTR * 2) + (kk + bcol) * 2;
                    ldsm_x4(bof + r16, q);
                    Bx[0][0] = q[0]; Bx[0][1] = q[1];
                    Bx[1][0] = q[2]; Bx[1][1] = q[3];
                    uint32_t r8 = (nb + 16 + brow2) * (BSTR * 2) + (kk + bcol2) * 2;
                    ldsm_x2(bof + r8, Bx[2]);
                }
                #pragma unroll
                for (int nt = 0; nt < 3; ++nt)
                    mma_f16(acc[nt], Ax, Bx[nt]);
            }
        }

        // write gh fragments (own region; no pre-sync needed)
        {
            int row0 = wm * 16 + (lane >> 2);
            int col0 = nb + (lane & 3) * 2;
            #pragma unroll
            for (int nt = 0; nt < 3; ++nt) {
                *(float2*)(gh + row0 * GH_STR + col0 + nt * 8) = make_float2(acc[nt][0], acc[nt][1]);
                *(float2*)(gh + (row0 + 8) * GH_STR + col0 + nt * 8) = make_float2(acc[nt][2], acc[nt][3]);
            }
        }
        __syncthreads();

        {
            __half2 grh = *(__half2*)&gru.x, grh2 = *(__half2*)&gru.y;
            __half2 gzh = *(__half2*)&gzu.x, gzh2 = *(__half2*)&gzu.y;
            __half2 gnh = *(__half2*)&gnu.x, gnh2 = *(__half2*)&gnu.y;
            float grv[4] = {__low2float(grh), __high2float(grh), __low2float(grh2), __high2float(grh2)};
            float gzv[4] = {__low2float(gzh), __high2float(gzh), __low2float(gzh2), __high2float(gzh2)};
            float gnv[4] = {__low2float(gnh), __high2float(gnh), __low2float(gnh2), __high2float(gnh2)};
            __half h16v[4];
            float hnew4[4];
            #pragma unroll
            for (int i = 0; i < 4; ++i) {
                int c = c0 + i;
                float ar = gh[gb * GH_STR + 0 * 16 + c];
                float az = gh[gb * GH_STR + 1 * 16 + c];
                float an = gh[gb * GH_STR + 2 * 16 + c];
                float rg = fast_sigmoid(grv[i] + ar + brt[i]);
                float zg = fast_sigmoid(gzv[i] + az + bzt[i]);
                float ng = fast_tanh(gnv[i] + bni[i] + rg * (an + bnh[i]));
                float hnew = (1.f - zg) * ng + zg * h_old[i];
                h_old[i] = hnew;               // exact fp32 state in registers
                hnew4[i] = hnew;
                h16v[i] = __float2half_rn(hnew);
            }
            size_t ho = (size_t)bglob * HID + gcol0;
            *(uint2*)(g_h16[nxt] + ho) = *(uint2*)h16v;
            if (s == STEPS - 1)
                *(float4*)(out + ho) = *(float4*)hnew4;
        }

        cntbar(bg0, 32u * (s + 2));
    }
}

// ---------------- launcher ----------------
extern "C" void kernel_launch(void* const* d_in, const int* in_sizes, int n_in,
                              void* d_out, int out_size) {
    const float* x   = (const float*)d_in[0];
    const float* wih = (const float*)d_in[1];
    const float* whh = (const float*)d_in[2];
    const float* bih = (const float*)d_in[3];
    const float* bhh = (const float*)d_in[4];
    float* out = (float*)d_out;

    cudaFuncSetAttribute(k_gru_recur, cudaFuncAttributeMaxDynamicSharedMemorySize,
                         REC2_SMEM);
    cudaFuncSetAttribute(k_gemm_gi, cudaFuncAttributeMaxDynamicSharedMemorySize,
                         GEMM_SMEM);

    k_w_convert<<<(GH * ISZ) / 1024, 256>>>(wih);
    k_x_transpose<<<dim3(STEPS / 32, ISZ / 32, BATCH), dim3(32, 8)>>>(x);
    k_gemm_gi<<<dim3(GH / 128, MROWS / 128), 256, GEMM_SMEM>>>();
    k_gru_recur<<<256, 128, REC2_SMEM>>>(whh, bih, bhh, out);
}

// round 14
// speedup vs baseline: 1.2882x; 1.2882x over previous
#include <cuda_runtime.h>
#include <cuda_fp16.h>
#include <cstdint>

#define BATCH 256
#define ISZ   512
#define STEPS 256
#define HID   512
#define GH    1536
#define NCTA  128
#define MROWS (STEPS * BATCH)     // 65536

// ---------------- scratch ----------------
__device__ __half g_x16[(size_t)MROWS * ISZ];
__device__ __half g_h16[2][BATCH * HID];
__device__ unsigned g_bg_cnt[4];

// ---------------- helpers ----------------
__device__ __forceinline__ uint32_t smem_to_u32(const void* p) {
    uint32_t a;
    asm("{ .reg .u64 t; cvta.to.shared.u64 t, %1; cvt.u32.u64 %0, t; }" : "=r"(a) : "l"(p));
    return a;
}
__device__ __forceinline__ void cp16(uint32_t dst, const void* src) {
    asm volatile("cp.async.cg.shared.global [%0], [%1], 16;" :: "r"(dst), "l"(src));
}
#define CP_COMMIT() asm volatile("cp.async.commit_group;" ::: "memory")
#define CP_WAIT(n)  asm volatile("cp.async.wait_group %0;" :: "n"(n) : "memory")

#define BARC() asm volatile("bar.sync 1, 256;" ::: "memory")   // consumer warps 0-7
#define BARP() asm volatile("bar.sync 2, 128;" ::: "memory")   // producer warps 8-11
#define BARA() asm volatile("bar.sync 3, 384;" ::: "memory")   // whole CTA

__device__ __forceinline__ void ldsm_x4(uint32_t addr, uint32_t r[4]) {
    asm volatile("ldmatrix.sync.aligned.m8n8.x4.shared.b16 {%0,%1,%2,%3}, [%4];"
                 : "=r"(r[0]), "=r"(r[1]), "=r"(r[2]), "=r"(r[3]) : "r"(addr));
}
__device__ __forceinline__ void ldsm_x2(uint32_t addr, uint32_t r[2]) {
    asm volatile("ldmatrix.sync.aligned.m8n8.x2.shared.b16 {%0,%1}, [%2];"
                 : "=r"(r[0]), "=r"(r[1]) : "r"(addr));
}
__device__ __forceinline__ void mma_f16(float d[4], const uint32_t a[4], const uint32_t b[2]) {
    asm volatile("mma.sync.aligned.m16n8k16.row.col.f32.f16.f16.f32 "
                 "{%0,%1,%2,%3}, {%4,%5,%6,%7}, {%8,%9}, {%0,%1,%2,%3};"
                 : "+f"(d[0]), "+f"(d[1]), "+f"(d[2]), "+f"(d[3])
                 : "r"(a[0]), "r"(a[1]), "r"(a[2]), "r"(a[3]), "r"(b[0]), "r"(b[1]));
}
__device__ __forceinline__ float fast_sigmoid(float v) {
    return __fdividef(1.f, 1.f + __expf(-v));
}
__device__ __forceinline__ float fast_tanh(float v) {
    float e = __expf(-2.f * v);
    return __fdividef(1.f - e, 1.f + e);
}

// ---------------- counter reset (stream-ordered before fused kernel) ----------------
__global__ void k_init() {
    if (threadIdx.x < 4) g_bg_cnt[threadIdx.x] = 0;
}

// ---------------- x [B][I][S] -> g_x16 [(s*B+b)][i] fp16 ----------------
__global__ void k_x_transpose(const float* __restrict__ x) {
    __shared__ float tile[32][33];
    int s0 = blockIdx.x * 32;
    int i0 = blockIdx.y * 32;
    int b  = blockIdx.z;
    int tx = threadIdx.x, ty = threadIdx.y;
    #pragma unroll
    for (int j = 0; j < 4; ++j)
        tile[ty + 8 * j][tx] = x[((size_t)b * ISZ + i0 + ty + 8 * j) * STEPS + s0 + tx];
    __syncthreads();
    #pragma unroll
    for (int j = 0; j < 4; ++j) {
        int s = s0 + ty + 8 * j;
        float v = tile[tx][ty + 8 * j];
        g_x16[((size_t)s * BATCH + b) * ISZ + i0 + tx] = __float2half_rn(v);
    }
}

// ---------------- fused persistent kernel ----------------
// 128 CTAs x 384 threads = 4 bg (64 rows) x 32 cg (16 cols x 3 gates).
// Warps 0-7 (256 thr): GRU recurrence consumer (R12-proven structure).
// Warps 8-11 (128 thr): gi producer — computes this CTA's gi block (64x48, K=512)
// from g_x16 and a resident Wih slice, into double-buffered smem. gi never in gmem.
#define BSTR 520
#define A_OFF  0                                 // h A tile: 64 rows x 1024B
#define BW_OFF 65536                             // Whh B: 48*BSTR*2 = 49920
#define GH_OFF (BW_OFF + 48 * BSTR * 2)          // 115456; gh: 64*50*4 = 12800
#define GH_STR 50
#define WI_OFF (GH_OFF + 64 * GH_STR * 4)        // 128256; Wih B: 49920
#define XB_OFF (WI_OFF + 48 * BSTR * 2)          // 178176; x bufs: 2 x 16384
#define GI_OFF (XB_OFF + 2 * 16384)              // 210944; gi bufs: 2 x 64*56*2
#define GI_STR 56
#define FUSED_SMEM (GI_OFF + 2 * 64 * GI_STR * 2)  // 225280

__device__ __forceinline__ uint32_t a_off(int row, int kb) {
    uint32_t u = ((uint32_t)kb >> 3) ^ (row & 7);
    return (uint32_t)row * 1024 + u * 16;
}
// x chunk tile: 64 rows x 128 halves (256B row), conflict-free swizzle
__device__ __forceinline__ uint32_t x_off(int row, int kb) {
    uint32_t unit = (uint32_t)kb >> 3;                      // 0..15
    uint32_t su = (unit & 8) | ((unit ^ (uint32_t)row) & 7);
    return (uint32_t)row * 256 + su * 16;
}

__device__ __forceinline__ void cntbar(int bg, unsigned target) {
    BARC();
    if (threadIdx.x == 0) {
        asm volatile("red.release.gpu.global.add.u32 [%0], %1;"
                     :: "l"(&g_bg_cnt[bg]), "r"(1u) : "memory");
        unsigned v;
        do {
            asm volatile("ld.global.acquire.gpu.u32 %0, [%1];"
                         : "=r"(v) : "l"(&g_bg_cnt[bg]) : "memory");
        } while (v < target);
    }
    BARC();
}

__global__ void __launch_bounds__(384, 1) k_fused(
    const float* __restrict__ wih, const float* __restrict__ whh,
    const float* __restrict__ bih, const float* __restrict__ bhh,
    float* __restrict__ out)
{
    extern __shared__ char smem[];
    uint32_t sb = smem_to_u32(smem);
    float* gh = (float*)(smem + GH_OFF);

    const int cta = blockIdx.x;
    const int cg  = cta & 31;
    const int bg0 = cta >> 5;
    const int tid = threadIdx.x;
    const int lane = tid & 31;
    const int wid = tid >> 5;

    // ldmatrix lane constants (shared by both roles)
    const int t4 = lane >> 3;
    const int arow = (t4 & 1) * 8 + (lane & 7);
    const int acol = (t4 >> 1) * 8;
    const int brow = (t4 >> 1) * 8 + (lane & 7);
    const int bcol = (t4 & 1) * 8;
    const int brow2 = lane & 7;
    const int bcol2 = ((lane >> 3) & 1) * 8;

    // ---- init: both weight slices -> fp16 smem (all 384 threads) ----
    for (int idx = tid; idx < 48 * 128; idx += 384) {
        int r = idx >> 7;
        int kq = idx & 127;
        int g = r >> 4, c = r & 15;
        size_t grow = (size_t)(g * HID + cg * 16 + c) * HID + kq * 4;
        float4 vh = *(const float4*)(whh + grow);
        float4 vi = *(const float4*)(wih + (size_t)(g * HID + cg * 16 + c) * ISZ + kq * 4);
        __half h4[4], i4[4];
        h4[0] = __float2half_rn(vh.x); h4[1] = __float2half_rn(vh.y);
        h4[2] = __float2half_rn(vh.z); h4[3] = __float2half_rn(vh.w);
        i4[0] = __float2half_rn(vi.x); i4[1] = __float2half_rn(vi.y);
        i4[2] = __float2half_rn(vi.z); i4[3] = __float2half_rn(vi.w);
        *(uint2*)(smem + BW_OFF + r * (BSTR * 2) + kq * 8) = *(uint2*)h4;
        *(uint2*)(smem + WI_OFF + r * (BSTR * 2) + kq * 8) = *(uint2*)i4;
    }
    if (tid < 128) {   // zero h buffer 0: 128 CTAs x 128 thr x 16B = 256KB exact
        uint4 z = make_uint4(0, 0, 0, 0);
        *(uint4*)((char*)g_h16[0] + ((size_t)cta * 128 + tid) * 16) = z;
    }
    __syncthreads();

    if (wid < 8) {
        // ================= CONSUMER: GRU recurrence =================
        const int wm = wid & 3;
        const int wn = wid >> 2;
        const int gb = tid >> 2;
        const int cq = tid & 3;
        const int c0 = cq * 4;
        const int gcol0 = cg * 16 + c0;
        float brt[4], bzt[4], bni[4], bnh[4];
        #pragma unroll
        for (int i = 0; i < 4; ++i) {
            brt[i] = bih[gcol0 + i] + bhh[gcol0 + i];
            bzt[i] = bih[HID + gcol0 + i] + bhh[HID + gcol0 + i];
            bni[i] = bih[2 * HID + gcol0 + i];
            bnh[i] = bhh[2 * HID + gcol0 + i];
        }
        float h_old[4] = {0.f, 0.f, 0.f, 0.f};

        cntbar(bg0, 32u);   // h zeros visible across the bg

        const uint32_t bof = sb + BW_OFF;
        const int nb = wn * 24;
        const int bglob = bg0 * 64 + gb;

        for (int s = 0; s < STEPS; ++s) {
            const int cur = s & 1, nxt = cur ^ 1;
            const __half* hsrc = g_h16[cur];

            // issue all 4 h-A chunks (deep pipeline)
            #pragma unroll
            for (int pre = 0; pre < 4; ++pre) {
                #pragma unroll
                for (int i = 0; i < 4; ++i) {
                    int lin = tid + 256 * i;
                    int row = lin >> 4;
                    int kb = pre * 128 + (lin & 15) * 8;
                    cp16(sb + A_OFF + a_off(row, kb),
                         hsrc + (size_t)(bg0 * 64 + row) * HID + kb);
                }
                CP_COMMIT();
            }

            float acc[3][4];
            #pragma unroll
            for (int j = 0; j < 3; ++j)
                #pragma unroll
                for (int v = 0; v < 4; ++v) acc[j][v] = 0.f;

            #pragma unroll
            for (int kc = 0; kc < 4; ++kc) {
                if (kc == 0)      CP_WAIT(3);
                else if (kc == 1) CP_WAIT(2);
                else if (kc == 2) CP_WAIT(1);
                else              CP_WAIT(0);
                BARC();

                #pragma unroll
                for (int t = 0; t < 8; ++t) {
                    const int kk = kc * 128 + t * 16;
                    uint32_t Ax[4], Bx[3][2];
                    {
                        int rr = wm * 16 + arow;
                        ldsm_x4(sb + A_OFF + a_off(rr, kk + acol), Ax);
                    }
                    {
                        uint32_t q[4];
                        uint32_t r16 = (nb + brow) * (BSTR * 2) + (kk + bcol) * 2;
                        ldsm_x4(bof + r16, q);
                        Bx[0][0] = q[0]; Bx[0][1] = q[1];
                        Bx[1][0] = q[2]; Bx[1][1] = q[3];
                        uint32_t r8 = (nb + 16 + brow2) * (BSTR * 2) + (kk + bcol2) * 2;
                        ldsm_x2(bof + r8, Bx[2]);
                    }
                    #pragma unroll
                    for (int nt = 0; nt < 3; ++nt)
                        mma_f16(acc[nt], Ax, Bx[nt]);
                }
            }

            // write gh fragments (own region); BARA below publishes them
            {
                int row0 = wm * 16 + (lane >> 2);
                int col0 = nb + (lane & 3) * 2;
                #pragma unroll
                for (int nt = 0; nt < 3; ++nt) {
                    *(float2*)(gh + row0 * GH_STR + col0 + nt * 8) = make_float2(acc[nt][0], acc[nt][1]);
                    *(float2*)(gh + (row0 + 8) * GH_STR + col0 + nt * 8) = make_float2(acc[nt][2], acc[nt][3]);
                }
            }

            BARA();   // gh done + gi[s] ready (producer side)

            {
                const __half* gib = (const __half*)(smem + GI_OFF + (s & 1) * (64 * GI_STR * 2));
                __half h16v[4];
                float hnew4[4];
                #pragma unroll
                for (int i = 0; i < 4; ++i) {
                    int c = c0 + i;
                    float gr = __half2float(gib[gb * GI_STR + 0 * 16 + c]);
                    float gz = __half2float(gib[gb * GI_STR + 1 * 16 + c]);
                    float gn = __half2float(gib[gb * GI_STR + 2 * 16 + c]);
                    float ar = gh[gb * GH_STR + 0 * 16 + c];
                    float az = gh[gb * GH_STR + 1 * 16 + c];
                    float an = gh[gb * GH_STR + 2 * 16 + c];
                    float rg = fast_sigmoid(gr + ar + brt[i]);
                    float zg = fast_sigmoid(gz + az + bzt[i]);
                    float ng = fast_tanh(gn + bni[i] + rg * (an + bnh[i]));
                    float hnew = (1.f - zg) * ng + zg * h_old[i];
                    h_old[i] = hnew;
                    hnew4[i] = hnew;
                    h16v[i] = __float2half_rn(hnew);
                }
                size_t ho = (size_t)bglob * HID + gcol0;
                *(uint2*)(g_h16[nxt] + ho) = *(uint2*)h16v;
                if (s == STEPS - 1)
                    *(float4*)(out + ho) = *(float4*)hnew4;
            }

            cntbar(bg0, 32u * (s + 2));
        }
    } else {
        // ================= PRODUCER: gi[s] = x(s,bg rows) @ Wih_slice^T =================
        const int p   = tid - 256;       // 0..127
        const int pw  = wid - 8;         // 0..3
        const int pwm = pw & 1;          // m half (32 rows via mt)
        const int pwn = pw >> 1;         // n half (24)
        const uint32_t wif = sb + WI_OFF;
        const int nb_p = pwn * 24;

        for (int s = 0; s < STEPS; ++s) {
            const size_t xrow0 = (size_t)s * BATCH + bg0 * 64;

            // issue x chunks 0,1
            #pragma unroll
            for (int pre = 0; pre < 2; ++pre) {
                #pragma unroll
                for (int i = 0; i < 8; ++i) {
                    int lin = p + 128 * i;           // 0..1023
                    int row = lin >> 4;
                    int unit = lin & 15;
                    cp16(sb + XB_OFF + pre * 16384 + x_off(row, unit * 8),
                         g_x16 + (xrow0 + row) * ISZ + pre * 128 + unit * 8);
                }
                CP_COMMIT();
            }

            float acc[2][3][4];
            #pragma unroll
            for (int m = 0; m < 2; ++m)
                #pragma unroll
                for (int j = 0; j < 3; ++j)
                    #pragma unroll
                    for (int v = 0; v < 4; ++v) acc[m][j][v] = 0.f;

            #pragma unroll
            for (int kc = 0; kc < 4; ++kc) {
                if (kc < 3) CP_WAIT(1); else CP_WAIT(0);
                BARP();
                const uint32_t xb = sb + XB_OFF + (kc & 1) * 16384;

                #pragma unroll
                for (int t = 0; t < 8; ++t) {
                    const int kkl = t * 16;          // within chunk
                    const int kk  = kc * 128 + kkl;  // within K=512 (for B)
                    uint32_t Bx[3][2];
                    {
                        uint32_t q[4];
                        uint32_t r16 = (nb_p + brow) * (BSTR * 2) + (kk + bcol) * 2;
                        ldsm_x4(wif + r16, q);
                        Bx[0][0] = q[0]; Bx[0][1] = q[1];
                        Bx[1][0] = q[2]; Bx[1][1] = q[3];
                        uint32_t r8 = (nb_p + 16 + brow2) * (BSTR * 2) + (kk + bcol2) * 2;
                        ldsm_x2(wif + r8, Bx[2]);
                    }
                    #pragma unroll
                    for (int mt = 0; mt < 2; ++mt) {
                        uint32_t Ax[4];
                        int rr = pwm * 32 + mt * 16 + arow;
                        ldsm_x4(xb + x_off(rr, kkl + acol), Ax);
                        #pragma unroll
                        for (int nt = 0; nt < 3; ++nt)
                            mma_f16(acc[mt][nt], Ax, Bx[nt]);
                    }
                }
                BARP();                               // all producer warps done with buf
                if (kc < 2) {                         // issue chunk kc+2 into freed buf
                    int pre = kc + 2;
                    #pragma unroll
                    for (int i = 0; i < 8; ++i) {
                        int lin = p + 128 * i;
                        int row = lin >> 4;
                        int unit = lin & 15;
                        cp16(sb + XB_OFF + (pre & 1) * 16384 + x_off(row, unit * 8),
                             g_x16 + (xrow0 + row) * ISZ + pre * 128 + unit * 8);
                    }
                    CP_COMMIT();
                }
            }

            // epilogue: gi fragments -> smem buf (parity s&1) as fp16
            {
                __half* gob = (__half*)(smem + GI_OFF + (s & 1) * (64 * GI_STR * 2));
                int col0 = nb_p + (lane & 3) * 2;
                #pragma unroll
                for (int mt = 0; mt < 2; ++mt) {
                    int row0 = pwm * 32 + mt * 16 + (lane >> 2);
                    #pragma unroll
                    for (int nt = 0; nt < 3; ++nt) {
                        *(__half2*)(gob + row0 * GI_STR + col0 + nt * 8) =
                            __floats2half2_rn(acc[mt][nt][0], acc[mt][nt][1]);
                        *(__half2*)(gob + (row0 + 8) * GI_STR + col0 + nt * 8) =
                            __floats2half2_rn(acc[mt][nt][2], acc[mt][nt][3]);
                    }
                }
            }

            BARA();   // publish gi[s]; consumer gate reads it after this
        }
    }
}

// ---------------- launcher ----------------
extern "C" void kernel_launch(void* const* d_in, const int* in_sizes, int n_in,
                              void* d_out, int out_size) {
    const float* x   = (const float*)d_in[0];
    const float* wih = (const float*)d_in[1];
    const float* whh = (const float*)d_in[2];
    const float* bih = (const float*)d_in[3];
    const float* bhh = (const float*)d_in[4];
    float* out = (float*)d_out;

    cudaFuncSetAttribute(k_fused, cudaFuncAttributeMaxDynamicSharedMemorySize,
                         FUSED_SMEM);

    k_init<<<1, 32>>>();
    k_x_transpose<<<dim3(STEPS / 32, ISZ / 32, BATCH), dim3(32, 8)>>>(x);
    k_fused<<<NCTA, 384, FUSED_SMEM>>>(wih, whh, bih, bhh, out);
}